// round 16
// baseline (speedup 1.0000x reference)
#include <cuda_runtime.h>
#include <cuda_bf16.h>
#include <math.h>
#include <stdint.h>

// ---------------------------------------------------------------------------
// GraphSimilarity: 2x { [enc1+enc2+conv1 fused 3-GEMM] -> agg -> conv2-GEMM
//                       -> agg+pool } -> similarity MLP -> scalar
// GEMMs on mma.sync (bf16 3-term split, fp32 acc); weights split from fp32
// in-kernel. CSR built scan-free (2 edges/thread, warp-aggregated offsets).
// Feature tensors packed bf16x2. Aggregates use small CTAs (2/4 warps) to
// cut degree-imbalance tail waste. Both graphs batched per launch.
// ---------------------------------------------------------------------------

#define MAXN 50000
#define MAXE 800000
#define HDIM 128
#define ICSR (2 * MAXN + 1)

__device__ __align__(16) float g_bufA[2][MAXN * HDIM];   // packed-u32 h images
__device__ __align__(16) float g_bufB[2][MAXN * HDIM];   // packed-u32 agg image
__device__ int   g_icsr[2][ICSR];     // deg | (unused) | gctr
__device__ int   g_erank[2][MAXE];
__device__ float g_dis[2][MAXN];
__device__ int   g_offs[2][MAXN];
__device__ int   g_csr_col[2][MAXE];
__device__ float g_gsum[2 * HDIM];

// ======================= helpers ===========================================
__device__ __forceinline__ uint32_t smem_u32(const void* p) {
    uint32_t a;
    asm("{ .reg .u64 t; cvta.to.shared.u64 t, %1; cvt.u32.u64 %0, t; }" : "=r"(a) : "l"(p));
    return a;
}
__device__ __forceinline__ void ldsm_x4(uint32_t addr, uint32_t r[4]) {
    asm volatile("ldmatrix.sync.aligned.m8n8.x4.shared.b16 {%0,%1,%2,%3}, [%4];"
                 : "=r"(r[0]), "=r"(r[1]), "=r"(r[2]), "=r"(r[3]) : "r"(addr));
}
__device__ __forceinline__ void ldsm_x4t(uint32_t addr, uint32_t r[4]) {
    asm volatile("ldmatrix.sync.aligned.m8n8.x4.trans.shared.b16 {%0,%1,%2,%3}, [%4];"
                 : "=r"(r[0]), "=r"(r[1]), "=r"(r[2]), "=r"(r[3]) : "r"(addr));
}
__device__ __forceinline__ void mma16816(float c[4], const uint32_t a[4],
                                         uint32_t b0, uint32_t b1) {
    asm volatile(
        "mma.sync.aligned.m16n8k16.row.col.f32.bf16.bf16.f32 "
        "{%0,%1,%2,%3}, {%4,%5,%6,%7}, {%8,%9}, {%0,%1,%2,%3};"
        : "+f"(c[0]), "+f"(c[1]), "+f"(c[2]), "+f"(c[3])
        : "r"(a[0]), "r"(a[1]), "r"(a[2]), "r"(a[3]), "r"(b0), "r"(b1));
}
__device__ __forceinline__ void split2(float v0, float v1, unsigned& hi, unsigned& lo) {
    unsigned h;
    asm("cvt.rn.bf16x2.f32 %0, %1, %2;" : "=r"(h) : "f"(v1), "f"(v0));
    float f0 = __uint_as_float(h << 16);
    float f1 = __uint_as_float(h & 0xFFFF0000u);
    float r0 = v0 - f0, r1 = v1 - f1;
    unsigned l;
    asm("cvt.rn.bf16x2.f32 %0, %1, %2;" : "=r"(l) : "f"(r1), "f"(r0));
    hi = h; lo = l;
}
__device__ __forceinline__ unsigned pack_bf16x2(float v0, float v1) {
    unsigned h;
    asm("cvt.rn.bf16x2.f32 %0, %1, %2;" : "=r"(h) : "f"(v1), "f"(v0));
    return h;
}

// ---------------------------------------------------------------------------
// GEMM tiling constants
// ---------------------------------------------------------------------------
#define ASTR 136
#define TH   (128 * ASTR)
#define TH64 (64 * ASTR)

#define E_AHI 0
#define E_ALO TH
#define E_B1HI (2 * TH)
#define E_B1LO (3 * TH)
#define E_B2HI (4 * TH)
#define E_B2LO (5 * TH)
#define SM_ENC3 (6 * TH * 2)

#define G_AHI 0
#define G_ALO TH64
#define G_BHI (2 * TH64)
#define G_BLO (2 * TH64 + TH)
#define SM_G64 ((2 * TH64 + 2 * TH) * 2)

__device__ __forceinline__ void gemm_mainloop(uint32_t aHi, uint32_t aLo,
                                              uint32_t bHi, uint32_t bLo,
                                              float acc[16][4])
{
#pragma unroll
    for (int ks = 0; ks < 8; ks++) {
        const uint32_t kb = (uint32_t)(ks * 16) * 2u;
        uint32_t ah[4], al[4];
        ldsm_x4(aHi + kb, ah);
        ldsm_x4(aLo + kb, al);
        const uint32_t kRowB = (uint32_t)(ks * 16 * ASTR) * 2u;
#pragma unroll
        for (int nb = 0; nb < 8; nb++) {
            uint32_t bh[4], bl[4];
            const uint32_t nOff = (uint32_t)(nb * 16) * 2u;
            ldsm_x4t(bHi + kRowB + nOff, bh);
            ldsm_x4t(bLo + kRowB + nOff, bl);
            mma16816(acc[nb * 2],     ah, bh[0], bh[1]);
            mma16816(acc[nb * 2 + 1], ah, bh[2], bh[3]);
            mma16816(acc[nb * 2],     ah, bl[0], bl[1]);
            mma16816(acc[nb * 2 + 1], ah, bl[2], bl[3]);
            mma16816(acc[nb * 2],     al, bh[0], bh[1]);
            mma16816(acc[nb * 2 + 1], al, bh[2], bh[3]);
        }
    }
}

// ---------------------------------------------------------------------------
// Fused encoder + conv1: h3 = (relu(X W1 + b1) W2 + b2) W3 + b3
// Weights split from fp32 in the prologue. Output packed bf16x2.
// ---------------------------------------------------------------------------
__global__ __launch_bounds__(256, 1)
void k_enc3(const float* __restrict__ x1, const float* __restrict__ x2,
            const float* __restrict__ ew1, const float* __restrict__ ew2,
            const float* __restrict__ cw1,
            const float* __restrict__ b1, const float* __restrict__ b2,
            const float* __restrict__ b3,
            unsigned* __restrict__ C0, int M, int tpg)
{
    extern __shared__ __nv_bfloat16 smh[];
    const uint32_t sb = smem_u32(smh);
    const int tid = threadIdx.x;
    const int wid = tid >> 5, lid = tid & 31;
    const int g = blockIdx.x / tpg;
    const int bm = (blockIdx.x % tpg) * 128;
    const float* X = g ? x2 : x1;
    unsigned* C = C0 + (size_t)g * MAXN * HDIM;

    // W1 -> slot1, W2 -> slot2 (split from fp32)
    for (int i = tid; i < 8192; i += 256) {
        int k = i >> 6, np = i & 63;
        int o = k * ASTR + np * 2;
        float2 wv = *(const float2*)(ew1 + (size_t)k * 128 + np * 2);
        unsigned h, l;
        split2(wv.x, wv.y, h, l);
        *(unsigned*)(smh + E_B1HI + o) = h;
        *(unsigned*)(smh + E_B1LO + o) = l;
        wv = *(const float2*)(ew2 + (size_t)k * 128 + np * 2);
        split2(wv.x, wv.y, h, l);
        *(unsigned*)(smh + E_B2HI + o) = h;
        *(unsigned*)(smh + E_B2LO + o) = l;
    }
    for (int i = tid; i < 4096; i += 256) {
        int r = i >> 5, c4 = (i & 31) * 4;
        int grow = bm + r;
        float4 v = make_float4(0.f, 0.f, 0.f, 0.f);
        if (grow < M) v = *(const float4*)(X + (size_t)grow * 128 + c4);
        unsigned h0, l0, h1, l1;
        split2(v.x, v.y, h0, l0);
        split2(v.z, v.w, h1, l1);
        unsigned* ph = (unsigned*)(smh + E_AHI + r * ASTR + c4);
        unsigned* pl = (unsigned*)(smh + E_ALO + r * ASTR + c4);
        ph[0] = h0; ph[1] = h1;
        pl[0] = l0; pl[1] = l1;
    }
    __syncthreads();

    const int wr = wid * 16;
    const int sub = lid >> 3, l7 = lid & 7;
    const uint32_t aHi = sb + (uint32_t)(E_AHI + (wr + (sub & 1) * 8 + l7) * ASTR + (sub >> 1) * 8) * 2u;
    const uint32_t aLo = aHi + (uint32_t)(TH * 2);
    const uint32_t bOff = (uint32_t)(((sub & 1) * 8 + l7) * ASTR + (sub >> 1) * 8) * 2u;
    const uint32_t b1Hi = sb + (uint32_t)(E_B1HI) * 2u + bOff;
    const uint32_t b1Lo = sb + (uint32_t)(E_B1LO) * 2u + bOff;
    const uint32_t b2Hi = sb + (uint32_t)(E_B2HI) * 2u + bOff;
    const uint32_t b2Lo = sb + (uint32_t)(E_B2LO) * 2u + bOff;

    const int gid = lid >> 2, tig = lid & 3;
    const int r0 = wr + gid;
    const int r1 = r0 + 8;

    float acc[16][4];
#pragma unroll
    for (int i = 0; i < 16; i++)
#pragma unroll
        for (int j = 0; j < 4; j++) acc[i][j] = 0.0f;

    // ---- GEMM 1: relu(X W1 + b1) -> A ----
    gemm_mainloop(aHi, aLo, b1Hi, b1Lo, acc);
#pragma unroll
    for (int nb = 0; nb < 16; nb++) {
        int col = nb * 8 + tig * 2;
        float2 bv = *(const float2*)(b1 + col);
        float v0 = fmaxf(acc[nb][0] + bv.x, 0.f);
        float v1 = fmaxf(acc[nb][1] + bv.y, 0.f);
        float v2 = fmaxf(acc[nb][2] + bv.x, 0.f);
        float v3 = fmaxf(acc[nb][3] + bv.y, 0.f);
        unsigned h, l;
        split2(v0, v1, h, l);
        *(unsigned*)(smh + E_AHI + r0 * ASTR + col) = h;
        *(unsigned*)(smh + E_ALO + r0 * ASTR + col) = l;
        split2(v2, v3, h, l);
        *(unsigned*)(smh + E_AHI + r1 * ASTR + col) = h;
        *(unsigned*)(smh + E_ALO + r1 * ASTR + col) = l;
        acc[nb][0] = 0.f; acc[nb][1] = 0.f; acc[nb][2] = 0.f; acc[nb][3] = 0.f;
    }
    __syncwarp();

    // ---- GEMM 2: (.) W2 + b2 -> A  (no relu) ----
    gemm_mainloop(aHi, aLo, b2Hi, b2Lo, acc);
#pragma unroll
    for (int nb = 0; nb < 16; nb++) {
        int col = nb * 8 + tig * 2;
        float2 bv = *(const float2*)(b2 + col);
        float v0 = acc[nb][0] + bv.x;
        float v1 = acc[nb][1] + bv.y;
        float v2 = acc[nb][2] + bv.x;
        float v3 = acc[nb][3] + bv.y;
        unsigned h, l;
        split2(v0, v1, h, l);
        *(unsigned*)(smh + E_AHI + r0 * ASTR + col) = h;
        *(unsigned*)(smh + E_ALO + r0 * ASTR + col) = l;
        split2(v2, v3, h, l);
        *(unsigned*)(smh + E_AHI + r1 * ASTR + col) = h;
        *(unsigned*)(smh + E_ALO + r1 * ASTR + col) = l;
        acc[nb][0] = 0.f; acc[nb][1] = 0.f; acc[nb][2] = 0.f; acc[nb][3] = 0.f;
    }

    // ---- reload W3 (conv1, split from fp32) into slot1 ----
    __syncthreads();
    for (int i = tid; i < 8192; i += 256) {
        int k = i >> 6, np = i & 63;
        int o = k * ASTR + np * 2;
        float2 wv = *(const float2*)(cw1 + (size_t)k * 128 + np * 2);
        unsigned h, l;
        split2(wv.x, wv.y, h, l);
        *(unsigned*)(smh + E_B1HI + o) = h;
        *(unsigned*)(smh + E_B1LO + o) = l;
    }
    __syncthreads();

    // ---- GEMM 3: (.) W3 + b3 -> gmem (packed bf16x2) ----
    gemm_mainloop(aHi, aLo, b1Hi, b1Lo, acc);
    const int row0 = bm + r0;
    const int row1 = bm + r1;
#pragma unroll
    for (int nb = 0; nb < 16; nb++) {
        int col = nb * 8 + tig * 2;
        float2 bv = *(const float2*)(b3 + col);
        int ci = nb * 4 + tig;
        if (row0 < M)
            C[(size_t)row0 * 64 + ci] = pack_bf16x2(acc[nb][0] + bv.x, acc[nb][1] + bv.y);
        if (row1 < M)
            C[(size_t)row1 * 64 + ci] = pack_bf16x2(acc[nb][2] + bv.x, acc[nb][3] + bv.y);
    }
}

// ---------------------------------------------------------------------------
// GCN-2 GEMM, BM=64 / 128 threads (2 CTAs/SM): C = relu(dis*A) @ W + bias
// Packed bf16x2 input (agg) and output; W split from fp32 in prologue.
// ---------------------------------------------------------------------------
__global__ __launch_bounds__(128, 2)
void k_gemm64(const unsigned* __restrict__ A0,
              const float* __restrict__ W,
              const float* __restrict__ bias, unsigned* __restrict__ C0,
              const float* __restrict__ dis0, int M, int tpg)
{
    extern __shared__ __nv_bfloat16 smh[];
    const uint32_t sb = smem_u32(smh);
    const int tid = threadIdx.x;
    const int wid = tid >> 5, lid = tid & 31;
    const int g = blockIdx.x / tpg;
    const int bm = (blockIdx.x % tpg) * 64;
    const unsigned* A = A0 + (size_t)g * MAXN * HDIM;
    unsigned* C       = C0 + (size_t)g * MAXN * HDIM;
    const float* dis  = dis0 + (size_t)g * MAXN;

    for (int i = tid; i < 8192; i += 128) {
        int k = i >> 6, np = i & 63;
        int o = k * ASTR + np * 2;
        float2 wv = *(const float2*)(W + (size_t)k * 128 + np * 2);
        unsigned h, l;
        split2(wv.x, wv.y, h, l);
        *(unsigned*)(smh + G_BHI + o) = h;
        *(unsigned*)(smh + G_BLO + o) = l;
    }
    // A tile: 64 rows x 16 uint4 (packed bf16x2, 8 cols per uint4)
    for (int i = tid; i < 1024; i += 128) {
        int r = i >> 4, q = i & 15;
        int grow = bm + r;
        float f[8] = {0.f, 0.f, 0.f, 0.f, 0.f, 0.f, 0.f, 0.f};
        if (grow < M) {
            uint4 p = __ldg((const uint4*)(A + (size_t)grow * 64) + q);
            float2 t;
            t = __bfloat1622float2(*reinterpret_cast<const __nv_bfloat162*>(&p.x));
            f[0] = t.x; f[1] = t.y;
            t = __bfloat1622float2(*reinterpret_cast<const __nv_bfloat162*>(&p.y));
            f[2] = t.x; f[3] = t.y;
            t = __bfloat1622float2(*reinterpret_cast<const __nv_bfloat162*>(&p.z));
            f[4] = t.x; f[5] = t.y;
            t = __bfloat1622float2(*reinterpret_cast<const __nv_bfloat162*>(&p.w));
            f[6] = t.x; f[7] = t.y;
            float dv = dis[grow];
#pragma unroll
            for (int j = 0; j < 8; j++) f[j] = fmaxf(f[j] * dv, 0.f);
        }
        unsigned hq[4], lq[4];
        split2(f[0], f[1], hq[0], lq[0]);
        split2(f[2], f[3], hq[1], lq[1]);
        split2(f[4], f[5], hq[2], lq[2]);
        split2(f[6], f[7], hq[3], lq[3]);
        *(uint4*)((char*)smh + (size_t)(G_AHI + r * ASTR + q * 8) * 2) =
            make_uint4(hq[0], hq[1], hq[2], hq[3]);
        *(uint4*)((char*)smh + (size_t)(G_ALO + r * ASTR + q * 8) * 2) =
            make_uint4(lq[0], lq[1], lq[2], lq[3]);
    }
    __syncthreads();

    const int wr = wid * 16;
    const int sub = lid >> 3, l7 = lid & 7;
    const uint32_t aHi = sb + (uint32_t)(G_AHI + (wr + (sub & 1) * 8 + l7) * ASTR + (sub >> 1) * 8) * 2u;
    const uint32_t aLo = aHi + (uint32_t)(TH64 * 2);
    const uint32_t bHi = sb + (uint32_t)(G_BHI + ((sub & 1) * 8 + l7) * ASTR + (sub >> 1) * 8) * 2u;
    const uint32_t bLo = bHi + (uint32_t)(TH * 2);

    float acc[16][4];
#pragma unroll
    for (int i = 0; i < 16; i++)
#pragma unroll
        for (int j = 0; j < 4; j++) acc[i][j] = 0.0f;

    gemm_mainloop(aHi, aLo, bHi, bLo, acc);

    const int gid = lid >> 2, tig = lid & 3;
    const int row0 = bm + wr + gid;
    const int row1 = row0 + 8;
#pragma unroll
    for (int nb = 0; nb < 16; nb++) {
        int col = nb * 8 + tig * 2;
        float2 bv = *(const float2*)(bias + col);
        int ci = nb * 4 + tig;
        if (row0 < M)
            C[(size_t)row0 * 64 + ci] = pack_bf16x2(acc[nb][0] + bv.x, acc[nb][1] + bv.y);
        if (row1 < M)
            C[(size_t)row1 * 64 + ci] = pack_bf16x2(acc[nb][2] + bv.x, acc[nb][3] + bv.y);
    }
}

// ---------------------------------------------------------------------------
// CSR build — 2 edges per thread; warp-aggregated global counter
// ---------------------------------------------------------------------------
__global__ void k_deg2(const int* __restrict__ ei1, const int* __restrict__ ei2,
                       int E, int* __restrict__ icsr0, int* __restrict__ erank0)
{
    int e = (blockIdx.x * blockDim.x + threadIdx.x) * 2;
    if (e >= E) return;
    const int* ei = blockIdx.y ? ei2 : ei1;
    int* deg = icsr0 + (size_t)blockIdx.y * ICSR;
    int* erank = erank0 + (size_t)blockIdx.y * MAXE;
    int2 r = *(const int2*)(ei + e);
    int k0 = atomicAdd(&deg[r.x], 1);
    int k1 = atomicAdd(&deg[r.y], 1);
    *(int2*)(erank + e) = make_int2(k0, k1);
}

__global__ void k_dis_offs2(int* __restrict__ icsr0, float* __restrict__ dis0,
                            int* __restrict__ offs0, int n)
{
    int i = blockIdx.x * blockDim.x + threadIdx.x;
    int lane = threadIdx.x & 31;
    int* deg  = icsr0 + (size_t)blockIdx.y * ICSR;
    int* gctr = deg + 2 * MAXN;
    float* dis = dis0 + (size_t)blockIdx.y * MAXN;
    int*   offs = offs0 + (size_t)blockIdx.y * MAXN;

    int d = (i < n) ? deg[i] : 0;
    if (i < n)
        dis[i] = (d > 0) ? rsqrtf((float)d) : 0.0f;

    int pre = d;
#pragma unroll
    for (int off = 1; off < 32; off <<= 1) {
        int t = __shfl_up_sync(0xFFFFFFFFu, pre, off);
        if (lane >= off) pre += t;
    }
    int total = __shfl_sync(0xFFFFFFFFu, pre, 31);
    int base = 0;
    if (lane == 31 && total > 0) base = atomicAdd(gctr, total);
    base = __shfl_sync(0xFFFFFFFFu, base, 31);
    if (i < n) offs[i] = base + pre - d;
}

__global__ void k_scatter2(const int* __restrict__ ei1, const int* __restrict__ ei2,
                           int E, const int* __restrict__ offs0,
                           const int* __restrict__ erank0, int* __restrict__ cols0)
{
    int e = (blockIdx.x * blockDim.x + threadIdx.x) * 2;
    if (e >= E) return;
    const int* ei = blockIdx.y ? ei2 : ei1;
    const int* offs = offs0 + (size_t)blockIdx.y * MAXN;
    const int* erank = erank0 + (size_t)blockIdx.y * MAXE;
    int* cols = cols0 + (size_t)blockIdx.y * MAXE;
    int2 r  = *(const int2*)(ei + e);
    int2 c  = *(const int2*)(ei + E + e);
    int2 rk = *(const int2*)(erank + e);
    int o0 = offs[r.x];
    int o1 = offs[r.y];
    cols[o0 + rk.x] = c.x;
    cols[o1 + rk.y] = c.y;
}

// ---------------------------------------------------------------------------
// edge-gather inner step (packed bf16x2 h rows, 256 B/row)
// ---------------------------------------------------------------------------
__device__ __forceinline__ void agg_step(const unsigned* __restrict__ h,
                                         const int* __restrict__ cols,
                                         const float* __restrict__ dis,
                                         int i, int lane, float4& a)
{
    int c = __ldg(cols + i);
    float nr = __ldg(dis + c);
    uint2 p = __ldg((const uint2*)(h + (size_t)c * 64) + lane);
    float2 f0 = __bfloat1622float2(*reinterpret_cast<const __nv_bfloat162*>(&p.x));
    float2 f1 = __bfloat1622float2(*reinterpret_cast<const __nv_bfloat162*>(&p.y));
    a.x = fmaf(nr, f0.x, a.x); a.y = fmaf(nr, f0.y, a.y);
    a.z = fmaf(nr, f1.x, a.z); a.w = fmaf(nr, f1.y, a.w);
}

// ---------------------------------------------------------------------------
// CSR aggregation (batched, 4-way unrolled), 64-thread CTAs (2 warps)
// ---------------------------------------------------------------------------
__global__ __launch_bounds__(64)
void k_aggregate(const unsigned* __restrict__ h0,
                 const int* __restrict__ offs0, const int* __restrict__ icsr0,
                 const int* __restrict__ cols0,
                 const float* __restrict__ dis0,
                 unsigned* __restrict__ agg0, int n, int bpg)
{
    const int g = blockIdx.x / bpg;
    const int lb = blockIdx.x % bpg;
    int warp = lb * (blockDim.x >> 5) + (threadIdx.x >> 5);
    int lane = threadIdx.x & 31;
    if (warp >= n) return;
    const unsigned* h = h0    + (size_t)g * MAXN * HDIM;
    unsigned* agg     = agg0  + (size_t)g * MAXN * HDIM;
    const int* offs   = offs0 + (size_t)g * MAXN;
    const int* deg    = icsr0 + (size_t)g * ICSR;
    const int* cols   = cols0 + (size_t)g * MAXE;
    const float* dis  = dis0  + (size_t)g * MAXN;

    int s = __ldg(offs + warp);
    int e = s + __ldg(deg + warp);
    float4 a0 = make_float4(0.f, 0.f, 0.f, 0.f);
    float4 a1 = make_float4(0.f, 0.f, 0.f, 0.f);
    float4 a2 = make_float4(0.f, 0.f, 0.f, 0.f);
    float4 a3 = make_float4(0.f, 0.f, 0.f, 0.f);
    int i = s;
    for (; i + 4 <= e; i += 4) {
        agg_step(h, cols, dis, i + 0, lane, a0);
        agg_step(h, cols, dis, i + 1, lane, a1);
        agg_step(h, cols, dis, i + 2, lane, a2);
        agg_step(h, cols, dis, i + 3, lane, a3);
    }
    if (i + 2 <= e) {
        agg_step(h, cols, dis, i + 0, lane, a0);
        agg_step(h, cols, dis, i + 1, lane, a1);
        i += 2;
    }
    if (i < e) agg_step(h, cols, dis, i, lane, a0);
    a0.x += a1.x + a2.x + a3.x;
    a0.y += a1.y + a2.y + a3.y;
    a0.z += a1.z + a2.z + a3.z;
    a0.w += a1.w + a2.w + a3.w;
    uint2 o;
    o.x = pack_bf16x2(a0.x, a0.y);
    o.y = pack_bf16x2(a0.z, a0.w);
    *(uint2*)(agg + (size_t)warp * 64 + lane * 2) = o;
}

// ---------------------------------------------------------------------------
// Fused aggregate + mean-pool (layer 2, batched), 128-thread CTAs (4 warps)
// ---------------------------------------------------------------------------
__global__ __launch_bounds__(128)
void k_aggpool(const unsigned* __restrict__ h0,
               const int* __restrict__ offs0, const int* __restrict__ icsr0,
               const int* __restrict__ cols0,
               const float* __restrict__ dis0,
               float* __restrict__ gsum0, int n, int bpg)
{
    __shared__ float gpart[128];
    gpart[threadIdx.x] = 0.0f;
    __syncthreads();

    const int g = blockIdx.x / bpg;
    const int lb = blockIdx.x % bpg;
    int warp = lb * (blockDim.x >> 5) + (threadIdx.x >> 5);
    int lane = threadIdx.x & 31;
    const unsigned* h = h0    + (size_t)g * MAXN * HDIM;
    const int* offs   = offs0 + (size_t)g * MAXN;
    const int* deg    = icsr0 + (size_t)g * ICSR;
    const int* cols   = cols0 + (size_t)g * MAXE;
    const float* dis  = dis0  + (size_t)g * MAXN;
    float* gsum       = gsum0 + (size_t)g * HDIM;

    if (warp < n) {
        int s = __ldg(offs + warp);
        int e = s + __ldg(deg + warp);
        float4 a0 = make_float4(0.f, 0.f, 0.f, 0.f);
        float4 a1 = make_float4(0.f, 0.f, 0.f, 0.f);
        float4 a2 = make_float4(0.f, 0.f, 0.f, 0.f);
        float4 a3 = make_float4(0.f, 0.f, 0.f, 0.f);
        int i = s;
        for (; i + 4 <= e; i += 4) {
            agg_step(h, cols, dis, i + 0, lane, a0);
            agg_step(h, cols, dis, i + 1, lane, a1);
            agg_step(h, cols, dis, i + 2, lane, a2);
            agg_step(h, cols, dis, i + 3, lane, a3);
        }
        if (i + 2 <= e) {
            agg_step(h, cols, dis, i + 0, lane, a0);
            agg_step(h, cols, dis, i + 1, lane, a1);
            i += 2;
        }
        if (i < e) agg_step(h, cols, dis, i, lane, a0);
        float d = __ldg(dis + warp);
        atomicAdd(&gpart[lane * 4 + 0], fmaxf(d * (a0.x + a1.x + a2.x + a3.x), 0.f));
        atomicAdd(&gpart[lane * 4 + 1], fmaxf(d * (a0.y + a1.y + a2.y + a3.y), 0.f));
        atomicAdd(&gpart[lane * 4 + 2], fmaxf(d * (a0.z + a1.z + a2.z + a3.z), 0.f));
        atomicAdd(&gpart[lane * 4 + 3], fmaxf(d * (a0.w + a1.w + a2.w + a3.w), 0.f));
    }
    __syncthreads();
    {
        float v = gpart[threadIdx.x];
        if (v != 0.0f) atomicAdd(&gsum[threadIdx.x], v);
    }
}

// ---------------------------------------------------------------------------
// final MLP
// ---------------------------------------------------------------------------
__global__ void k_final(const float* __restrict__ gsum,
                        const float* __restrict__ w1, const float* __restrict__ b1,
                        const float* __restrict__ w2, const float* __restrict__ b2,
                        float* __restrict__ out, float invN)
{
    __shared__ float cv[512];
    __shared__ float red[128];
    int t = threadIdx.x;
    float a = gsum[t] * invN;
    float b = gsum[128 + t] * invN;
    cv[t]       = a;
    cv[128 + t] = b;
    cv[256 + t] = fabsf(a - b);
    cv[384 + t] = a * b;
    __syncthreads();
    float acc = b1[t];
    for (int k = 0; k < 512; k++)
        acc = fmaf(cv[k], w1[k * 128 + t], acc);
    acc = fmaxf(acc, 0.f);
    red[t] = acc * w2[t];
    __syncthreads();
    for (int s = 64; s > 0; s >>= 1) {
        if (t < s) red[t] += red[t + s];
        __syncthreads();
    }
    if (t == 0) out[0] = red[0] + b2[0];
}

// ---------------------------------------------------------------------------
// launch — single stream, both graphs batched per kernel
// ---------------------------------------------------------------------------
extern "C" void kernel_launch(void* const* d_in, const int* in_sizes, int n_in,
                              void* d_out, int out_size)
{
    const float* x1  = (const float*)d_in[0];
    const int*   ei1 = (const int*)d_in[1];
    const float* x2  = (const float*)d_in[2];
    const int*   ei2 = (const int*)d_in[3];
    const float* enc_w1 = (const float*)d_in[4];
    const float* enc_b1 = (const float*)d_in[5];
    const float* enc_w2 = (const float*)d_in[6];
    const float* enc_b2 = (const float*)d_in[7];
    const float* conv1_w = (const float*)d_in[8];
    const float* conv1_b = (const float*)d_in[9];
    const float* conv2_w = (const float*)d_in[10];
    const float* conv2_b = (const float*)d_in[11];
    const float* sim_w1 = (const float*)d_in[12];
    const float* sim_b1 = (const float*)d_in[13];
    const float* sim_w2 = (const float*)d_in[14];
    const float* sim_b2 = (const float*)d_in[15];

    const int n = in_sizes[0] / HDIM;
    const int E = in_sizes[1] / 2;

    float *bufA, *bufB, *dis, *gsum;
    int *icsr, *offs, *cols, *erank;
    cudaGetSymbolAddress((void**)&bufA,  g_bufA);
    cudaGetSymbolAddress((void**)&bufB,  g_bufB);
    cudaGetSymbolAddress((void**)&icsr,  g_icsr);
    cudaGetSymbolAddress((void**)&erank, g_erank);
    cudaGetSymbolAddress((void**)&dis,   g_dis);
    cudaGetSymbolAddress((void**)&offs,  g_offs);
    cudaGetSymbolAddress((void**)&cols,  g_csr_col);
    cudaGetSymbolAddress((void**)&gsum,  g_gsum);

    cudaFuncSetAttribute(k_enc3,   cudaFuncAttributeMaxDynamicSharedMemorySize, SM_ENC3);
    cudaFuncSetAttribute(k_gemm64, cudaFuncAttributeMaxDynamicSharedMemorySize, SM_G64);

    const int tpg128   = (n + 127) / 128;
    const int tpg64    = (n + 63) / 64;
    const int e2Blocks = (E / 2 + 255) / 256;
    const int nBlocks  = (n + 255) / 256;
    const int bpgA     = (n + 1) / 2;      // aggregate: 2 warps/CTA
    const int bpgP     = (n + 3) / 4;      // aggpool:   4 warps/CTA

    // --- prep ---
    cudaMemsetAsync(gsum, 0, 2 * HDIM * sizeof(float));
    cudaMemsetAsync(icsr, 0, 2 * ICSR * sizeof(int));

    // --- CSR build (both graphs) ---
    {
        dim3 gE(e2Blocks, 2), gN(nBlocks, 2);
        k_deg2<<<gE, 256>>>(ei1, ei2, E, icsr, erank);
        k_dis_offs2<<<gN, 256>>>(icsr, dis, offs, n);
        k_scatter2<<<gE, 256>>>(ei1, ei2, E, offs, erank, cols);
    }

    // --- fused encoder + conv1 (both graphs) -> bufA (packed bf16x2) ---
    k_enc3<<<2 * tpg128, 256, SM_ENC3>>>(x1, x2, enc_w1, enc_w2, conv1_w,
                                         enc_b1, enc_b2, conv1_b,
                                         (unsigned*)bufA, n, tpg128);

    // --- aggregate 1 -> bufB (packed bf16x2) ---
    k_aggregate<<<2 * bpgA, 64>>>((const unsigned*)bufA, offs, icsr, cols, dis,
                                  (unsigned*)bufB, n, bpgA);

    // --- GCN layer 2 GEMM (relu(dis*agg) fused) -> bufA (packed bf16x2) ---
    k_gemm64<<<2 * tpg64, 128, SM_G64>>>((const unsigned*)bufB, conv2_w,
                                         conv2_b, (unsigned*)bufA, dis, n, tpg64);

    // --- aggregate 2 + mean pool -> gsum ---
    k_aggpool<<<2 * bpgP, 128>>>((const unsigned*)bufA, offs, icsr, cols, dis,
                                 gsum, n, bpgP);

    // --- final MLP ---
    k_final<<<1, 128>>>(gsum, sim_w1, sim_b1, sim_w2, sim_b2,
                        (float*)d_out, 1.0f / (float)n);
}

// round 17
// speedup vs baseline: 1.1534x; 1.1534x over previous
#include <cuda_runtime.h>
#include <cuda_bf16.h>
#include <math.h>
#include <stdint.h>

// ---------------------------------------------------------------------------
// GraphSimilarity: 2x { [enc1+enc2+conv1 fused 3-GEMM] -> agg -> conv2-GEMM
//                       -> agg+pool } -> similarity MLP -> scalar
// GEMMs on mma.sync (bf16 3-term split, fp32 acc). CSR built scan-free,
// scatter without cursor atomics (2 edges/thread). All inter-kernel feature
// tensors stored packed bf16x2 (gather + agg traffic halved).
// Both graphs batched into every kernel launch (single stream).
// (R13 configuration — measured best; R14/R16 deviations reverted.)
// ---------------------------------------------------------------------------

#define MAXN 50000
#define MAXE 800000
#define HDIM 128
#define ICSR (2 * MAXN + 1)

__device__ __align__(16) float g_bufA[2][MAXN * HDIM];   // packed-u32 h images
__device__ __align__(16) float g_bufB[2][MAXN * HDIM];   // packed-u32 agg image
__device__ int   g_icsr[2][ICSR];     // deg | (unused) | gctr
__device__ int   g_erank[2][MAXE];
__device__ float g_dis[2][MAXN];
__device__ int   g_offs[2][MAXN];
__device__ int   g_csr_col[2][MAXE];
__device__ float g_gsum[2 * HDIM];
__device__ __align__(16) unsigned g_wbf[8][8192];

// ======================= helpers ===========================================
__device__ __forceinline__ uint32_t smem_u32(const void* p) {
    uint32_t a;
    asm("{ .reg .u64 t; cvta.to.shared.u64 t, %1; cvt.u32.u64 %0, t; }" : "=r"(a) : "l"(p));
    return a;
}
__device__ __forceinline__ void ldsm_x4(uint32_t addr, uint32_t r[4]) {
    asm volatile("ldmatrix.sync.aligned.m8n8.x4.shared.b16 {%0,%1,%2,%3}, [%4];"
                 : "=r"(r[0]), "=r"(r[1]), "=r"(r[2]), "=r"(r[3]) : "r"(addr));
}
__device__ __forceinline__ void ldsm_x4t(uint32_t addr, uint32_t r[4]) {
    asm volatile("ldmatrix.sync.aligned.m8n8.x4.trans.shared.b16 {%0,%1,%2,%3}, [%4];"
                 : "=r"(r[0]), "=r"(r[1]), "=r"(r[2]), "=r"(r[3]) : "r"(addr));
}
__device__ __forceinline__ void mma16816(float c[4], const uint32_t a[4],
                                         uint32_t b0, uint32_t b1) {
    asm volatile(
        "mma.sync.aligned.m16n8k16.row.col.f32.bf16.bf16.f32 "
        "{%0,%1,%2,%3}, {%4,%5,%6,%7}, {%8,%9}, {%0,%1,%2,%3};"
        : "+f"(c[0]), "+f"(c[1]), "+f"(c[2]), "+f"(c[3])
        : "r"(a[0]), "r"(a[1]), "r"(a[2]), "r"(a[3]), "r"(b0), "r"(b1));
}
__device__ __forceinline__ void split2(float v0, float v1, unsigned& hi, unsigned& lo) {
    unsigned h;
    asm("cvt.rn.bf16x2.f32 %0, %1, %2;" : "=r"(h) : "f"(v1), "f"(v0));
    float f0 = __uint_as_float(h << 16);
    float f1 = __uint_as_float(h & 0xFFFF0000u);
    float r0 = v0 - f0, r1 = v1 - f1;
    unsigned l;
    asm("cvt.rn.bf16x2.f32 %0, %1, %2;" : "=r"(l) : "f"(r1), "f"(r0));
    hi = h; lo = l;
}
__device__ __forceinline__ unsigned pack_bf16x2(float v0, float v1) {
    unsigned h;
    asm("cvt.rn.bf16x2.f32 %0, %1, %2;" : "=r"(h) : "f"(v1), "f"(v0));
    return h;
}

// ---------------------------------------------------------------------------
// Weight prep
// ---------------------------------------------------------------------------
__global__ void k_convw(const float* __restrict__ w0, const float* __restrict__ w1,
                        const float* __restrict__ w2, const float* __restrict__ w3,
                        unsigned* __restrict__ wbf)
{
    int idx = blockIdx.x * blockDim.x + threadIdx.x;
    if (idx >= 8192) return;
    const float* W = (blockIdx.y == 0) ? w0 : (blockIdx.y == 1) ? w1
                   : (blockIdx.y == 2) ? w2 : w3;
    unsigned* hi = wbf + (size_t)(2 * blockIdx.y) * 8192;
    unsigned* lo = hi + 8192;
    int k = idx >> 6;
    int n = (idx & 63) * 2;
    unsigned h, l;
    split2(W[(size_t)k * 128 + n], W[(size_t)k * 128 + n + 1], h, l);
    hi[idx] = h;
    lo[idx] = l;
}

// ---------------------------------------------------------------------------
// GEMM tiling constants
// ---------------------------------------------------------------------------
#define ASTR 136
#define TH   (128 * ASTR)
#define TH64 (64 * ASTR)

#define E_AHI 0
#define E_ALO TH
#define E_B1HI (2 * TH)
#define E_B1LO (3 * TH)
#define E_B2HI (4 * TH)
#define E_B2LO (5 * TH)
#define SM_ENC3 (6 * TH * 2)

#define G_AHI 0
#define G_ALO TH64
#define G_BHI (2 * TH64)
#define G_BLO (2 * TH64 + TH)
#define SM_G64 ((2 * TH64 + 2 * TH) * 2)

__device__ __forceinline__ void gemm_mainloop(uint32_t aHi, uint32_t aLo,
                                              uint32_t bHi, uint32_t bLo,
                                              float acc[16][4])
{
#pragma unroll
    for (int ks = 0; ks < 8; ks++) {
        const uint32_t kb = (uint32_t)(ks * 16) * 2u;
        uint32_t ah[4], al[4];
        ldsm_x4(aHi + kb, ah);
        ldsm_x4(aLo + kb, al);
        const uint32_t kRowB = (uint32_t)(ks * 16 * ASTR) * 2u;
#pragma unroll
        for (int nb = 0; nb < 8; nb++) {
            uint32_t bh[4], bl[4];
            const uint32_t nOff = (uint32_t)(nb * 16) * 2u;
            ldsm_x4t(bHi + kRowB + nOff, bh);
            ldsm_x4t(bLo + kRowB + nOff, bl);
            mma16816(acc[nb * 2],     ah, bh[0], bh[1]);
            mma16816(acc[nb * 2 + 1], ah, bh[2], bh[3]);
            mma16816(acc[nb * 2],     ah, bl[0], bl[1]);
            mma16816(acc[nb * 2 + 1], ah, bl[2], bl[3]);
            mma16816(acc[nb * 2],     al, bh[0], bh[1]);
            mma16816(acc[nb * 2 + 1], al, bh[2], bh[3]);
        }
    }
}

// ---------------------------------------------------------------------------
// Fused encoder + conv1: h3 = (relu(X W1 + b1) W2 + b2) W3 + b3
// Output written as packed bf16x2 rows (64 u32 = 256 B per row).
// ---------------------------------------------------------------------------
__global__ __launch_bounds__(256, 1)
void k_enc3(const float* __restrict__ x1, const float* __restrict__ x2,
            const unsigned* __restrict__ wbf,
            const float* __restrict__ b1, const float* __restrict__ b2,
            const float* __restrict__ b3,
            unsigned* __restrict__ C0, int M, int tpg)
{
    extern __shared__ __nv_bfloat16 smh[];
    const uint32_t sb = smem_u32(smh);
    const int tid = threadIdx.x;
    const int wid = tid >> 5, lid = tid & 31;
    const int g = blockIdx.x / tpg;
    const int bm = (blockIdx.x % tpg) * 128;
    const float* X = g ? x2 : x1;
    unsigned* C = C0 + (size_t)g * MAXN * HDIM;

    for (int i = tid; i < 8192; i += 256) {
        int k = i >> 6, np = i & 63;
        int o = k * ASTR + np * 2;
        *(unsigned*)(smh + E_B1HI + o) = __ldg(wbf + i);
        *(unsigned*)(smh + E_B1LO + o) = __ldg(wbf + 8192 + i);
        *(unsigned*)(smh + E_B2HI + o) = __ldg(wbf + 16384 + i);
        *(unsigned*)(smh + E_B2LO + o) = __ldg(wbf + 24576 + i);
    }
    for (int i = tid; i < 4096; i += 256) {
        int r = i >> 5, c4 = (i & 31) * 4;
        int grow = bm + r;
        float4 v = make_float4(0.f, 0.f, 0.f, 0.f);
        if (grow < M) v = *(const float4*)(X + (size_t)grow * 128 + c4);
        unsigned h0, l0, h1, l1;
        split2(v.x, v.y, h0, l0);
        split2(v.z, v.w, h1, l1);
        unsigned* ph = (unsigned*)(smh + E_AHI + r * ASTR + c4);
        unsigned* pl = (unsigned*)(smh + E_ALO + r * ASTR + c4);
        ph[0] = h0; ph[1] = h1;
        pl[0] = l0; pl[1] = l1;
    }
    __syncthreads();

    const int wr = wid * 16;
    const int sub = lid >> 3, l7 = lid & 7;
    const uint32_t aHi = sb + (uint32_t)(E_AHI + (wr + (sub & 1) * 8 + l7) * ASTR + (sub >> 1) * 8) * 2u;
    const uint32_t aLo = aHi + (uint32_t)(TH * 2);
    const uint32_t bOff = (uint32_t)(((sub & 1) * 8 + l7) * ASTR + (sub >> 1) * 8) * 2u;
    const uint32_t b1Hi = sb + (uint32_t)(E_B1HI) * 2u + bOff;
    const uint32_t b1Lo = sb + (uint32_t)(E_B1LO) * 2u + bOff;
    const uint32_t b2Hi = sb + (uint32_t)(E_B2HI) * 2u + bOff;
    const uint32_t b2Lo = sb + (uint32_t)(E_B2LO) * 2u + bOff;

    const int gid = lid >> 2, tig = lid & 3;
    const int r0 = wr + gid;
    const int r1 = r0 + 8;

    float acc[16][4];
#pragma unroll
    for (int i = 0; i < 16; i++)
#pragma unroll
        for (int j = 0; j < 4; j++) acc[i][j] = 0.0f;

    // ---- GEMM 1: relu(X W1 + b1) -> A ----
    gemm_mainloop(aHi, aLo, b1Hi, b1Lo, acc);
#pragma unroll
    for (int nb = 0; nb < 16; nb++) {
        int col = nb * 8 + tig * 2;
        float2 bv = *(const float2*)(b1 + col);
        float v0 = fmaxf(acc[nb][0] + bv.x, 0.f);
        float v1 = fmaxf(acc[nb][1] + bv.y, 0.f);
        float v2 = fmaxf(acc[nb][2] + bv.x, 0.f);
        float v3 = fmaxf(acc[nb][3] + bv.y, 0.f);
        unsigned h, l;
        split2(v0, v1, h, l);
        *(unsigned*)(smh + E_AHI + r0 * ASTR + col) = h;
        *(unsigned*)(smh + E_ALO + r0 * ASTR + col) = l;
        split2(v2, v3, h, l);
        *(unsigned*)(smh + E_AHI + r1 * ASTR + col) = h;
        *(unsigned*)(smh + E_ALO + r1 * ASTR + col) = l;
        acc[nb][0] = 0.f; acc[nb][1] = 0.f; acc[nb][2] = 0.f; acc[nb][3] = 0.f;
    }
    __syncwarp();

    // ---- GEMM 2: (.) W2 + b2 -> A  (no relu) ----
    gemm_mainloop(aHi, aLo, b2Hi, b2Lo, acc);
#pragma unroll
    for (int nb = 0; nb < 16; nb++) {
        int col = nb * 8 + tig * 2;
        float2 bv = *(const float2*)(b2 + col);
        float v0 = acc[nb][0] + bv.x;
        float v1 = acc[nb][1] + bv.y;
        float v2 = acc[nb][2] + bv.x;
        float v3 = acc[nb][3] + bv.y;
        unsigned h, l;
        split2(v0, v1, h, l);
        *(unsigned*)(smh + E_AHI + r0 * ASTR + col) = h;
        *(unsigned*)(smh + E_ALO + r0 * ASTR + col) = l;
        split2(v2, v3, h, l);
        *(unsigned*)(smh + E_AHI + r1 * ASTR + col) = h;
        *(unsigned*)(smh + E_ALO + r1 * ASTR + col) = l;
        acc[nb][0] = 0.f; acc[nb][1] = 0.f; acc[nb][2] = 0.f; acc[nb][3] = 0.f;
    }

    // ---- reload W3 (conv1) into slot1 ----
    __syncthreads();
    for (int i = tid; i < 8192; i += 256) {
        int k = i >> 6, np = i & 63;
        int o = k * ASTR + np * 2;
        *(unsigned*)(smh + E_B1HI + o) = __ldg(wbf + 32768 + i);
        *(unsigned*)(smh + E_B1LO + o) = __ldg(wbf + 40960 + i);
    }
    __syncthreads();

    // ---- GEMM 3: (.) W3 + b3 -> gmem (packed bf16x2) ----
    gemm_mainloop(aHi, aLo, b1Hi, b1Lo, acc);
    const int row0 = bm + r0;
    const int row1 = bm + r1;
#pragma unroll
    for (int nb = 0; nb < 16; nb++) {
        int col = nb * 8 + tig * 2;
        float2 bv = *(const float2*)(b3 + col);
        int ci = nb * 4 + tig;
        if (row0 < M)
            C[(size_t)row0 * 64 + ci] = pack_bf16x2(acc[nb][0] + bv.x, acc[nb][1] + bv.y);
        if (row1 < M)
            C[(size_t)row1 * 64 + ci] = pack_bf16x2(acc[nb][2] + bv.x, acc[nb][3] + bv.y);
    }
}

// ---------------------------------------------------------------------------
// GCN-2 GEMM, BM=64 / 128 threads (2 CTAs/SM): C = relu(dis*A) @ W + bias
// Packed bf16x2 input (agg) and output.
// ---------------------------------------------------------------------------
__global__ __launch_bounds__(128, 2)
void k_gemm64(const unsigned* __restrict__ A0,
              const unsigned* __restrict__ whi, const unsigned* __restrict__ wlo,
              const float* __restrict__ bias, unsigned* __restrict__ C0,
              const float* __restrict__ dis0, int M, int tpg)
{
    extern __shared__ __nv_bfloat16 smh[];
    const uint32_t sb = smem_u32(smh);
    const int tid = threadIdx.x;
    const int wid = tid >> 5, lid = tid & 31;
    const int g = blockIdx.x / tpg;
    const int bm = (blockIdx.x % tpg) * 64;
    const unsigned* A = A0 + (size_t)g * MAXN * HDIM;
    unsigned* C       = C0 + (size_t)g * MAXN * HDIM;
    const float* dis  = dis0 + (size_t)g * MAXN;

    for (int i = tid; i < 8192; i += 128) {
        int k = i >> 6, np = i & 63;
        int o = k * ASTR + np * 2;
        *(unsigned*)(smh + G_BHI + o) = __ldg(whi + i);
        *(unsigned*)(smh + G_BLO + o) = __ldg(wlo + i);
    }
    // A tile: 64 rows x 16 uint4 (packed bf16x2, 8 cols per uint4)
    for (int i = tid; i < 1024; i += 128) {
        int r = i >> 4, q = i & 15;
        int grow = bm + r;
        float f[8] = {0.f, 0.f, 0.f, 0.f, 0.f, 0.f, 0.f, 0.f};
        if (grow < M) {
            uint4 p = __ldg((const uint4*)(A + (size_t)grow * 64) + q);
            float2 t;
            t = __bfloat1622float2(*reinterpret_cast<const __nv_bfloat162*>(&p.x));
            f[0] = t.x; f[1] = t.y;
            t = __bfloat1622float2(*reinterpret_cast<const __nv_bfloat162*>(&p.y));
            f[2] = t.x; f[3] = t.y;
            t = __bfloat1622float2(*reinterpret_cast<const __nv_bfloat162*>(&p.z));
            f[4] = t.x; f[5] = t.y;
            t = __bfloat1622float2(*reinterpret_cast<const __nv_bfloat162*>(&p.w));
            f[6] = t.x; f[7] = t.y;
            float dv = dis[grow];
#pragma unroll
            for (int j = 0; j < 8; j++) f[j] = fmaxf(f[j] * dv, 0.f);
        }
        unsigned hq[4], lq[4];
        split2(f[0], f[1], hq[0], lq[0]);
        split2(f[2], f[3], hq[1], lq[1]);
        split2(f[4], f[5], hq[2], lq[2]);
        split2(f[6], f[7], hq[3], lq[3]);
        *(uint4*)((char*)smh + (size_t)(G_AHI + r * ASTR + q * 8) * 2) =
            make_uint4(hq[0], hq[1], hq[2], hq[3]);
        *(uint4*)((char*)smh + (size_t)(G_ALO + r * ASTR + q * 8) * 2) =
            make_uint4(lq[0], lq[1], lq[2], lq[3]);
    }
    __syncthreads();

    const int wr = wid * 16;
    const int sub = lid >> 3, l7 = lid & 7;
    const uint32_t aHi = sb + (uint32_t)(G_AHI + (wr + (sub & 1) * 8 + l7) * ASTR + (sub >> 1) * 8) * 2u;
    const uint32_t aLo = aHi + (uint32_t)(TH64 * 2);
    const uint32_t bHi = sb + (uint32_t)(G_BHI + ((sub & 1) * 8 + l7) * ASTR + (sub >> 1) * 8) * 2u;
    const uint32_t bLo = bHi + (uint32_t)(TH * 2);

    float acc[16][4];
#pragma unroll
    for (int i = 0; i < 16; i++)
#pragma unroll
        for (int j = 0; j < 4; j++) acc[i][j] = 0.0f;

    gemm_mainloop(aHi, aLo, bHi, bLo, acc);

    const int gid = lid >> 2, tig = lid & 3;
    const int row0 = bm + wr + gid;
    const int row1 = row0 + 8;
#pragma unroll
    for (int nb = 0; nb < 16; nb++) {
        int col = nb * 8 + tig * 2;
        float2 bv = *(const float2*)(bias + col);
        int ci = nb * 4 + tig;
        if (row0 < M)
            C[(size_t)row0 * 64 + ci] = pack_bf16x2(acc[nb][0] + bv.x, acc[nb][1] + bv.y);
        if (row1 < M)
            C[(size_t)row1 * 64 + ci] = pack_bf16x2(acc[nb][2] + bv.x, acc[nb][3] + bv.y);
    }
}

// ---------------------------------------------------------------------------
// CSR build — 2 edges per thread
// ---------------------------------------------------------------------------
__global__ void k_deg2(const int* __restrict__ ei1, const int* __restrict__ ei2,
                       int E, int* __restrict__ icsr0, int* __restrict__ erank0)
{
    int e = (blockIdx.x * blockDim.x + threadIdx.x) * 2;
    if (e >= E) return;
    const int* ei = blockIdx.y ? ei2 : ei1;
    int* deg = icsr0 + (size_t)blockIdx.y * ICSR;
    int* erank = erank0 + (size_t)blockIdx.y * MAXE;
    int2 r = *(const int2*)(ei + e);
    int k0 = atomicAdd(&deg[r.x], 1);
    int k1 = atomicAdd(&deg[r.y], 1);
    *(int2*)(erank + e) = make_int2(k0, k1);
}

__global__ void k_dis_offs2(int* __restrict__ icsr0, float* __restrict__ dis0,
                            int* __restrict__ offs0, int n)
{
    int i = blockIdx.x * blockDim.x + threadIdx.x;
    if (i >= n) return;
    int* deg  = icsr0 + (size_t)blockIdx.y * ICSR;
    int* gctr = deg + 2 * MAXN;
    float* dis = dis0 + (size_t)blockIdx.y * MAXN;
    int*   offs = offs0 + (size_t)blockIdx.y * MAXN;
    int d = deg[i];
    dis[i] = (d > 0) ? rsqrtf((float)d) : 0.0f;
    offs[i] = atomicAdd(gctr, d);
}

__global__ void k_scatter2(const int* __restrict__ ei1, const int* __restrict__ ei2,
                           int E, const int* __restrict__ offs0,
                           const int* __restrict__ erank0, int* __restrict__ cols0)
{
    int e = (blockIdx.x * blockDim.x + threadIdx.x) * 2;
    if (e >= E) return;
    const int* ei = blockIdx.y ? ei2 : ei1;
    const int* offs = offs0 + (size_t)blockIdx.y * MAXN;
    const int* erank = erank0 + (size_t)blockIdx.y * MAXE;
    int* cols = cols0 + (size_t)blockIdx.y * MAXE;
    int2 r  = *(const int2*)(ei + e);
    int2 c  = *(const int2*)(ei + E + e);
    int2 rk = *(const int2*)(erank + e);
    int o0 = offs[r.x];
    int o1 = offs[r.y];
    cols[o0 + rk.x] = c.x;
    cols[o1 + rk.y] = c.y;
}

// ---------------------------------------------------------------------------
// edge-gather inner step (packed bf16x2 h rows, 256 B/row)
// ---------------------------------------------------------------------------
__device__ __forceinline__ void agg_step(const unsigned* __restrict__ h,
                                         const int* __restrict__ cols,
                                         const float* __restrict__ dis,
                                         int i, int lane, float4& a)
{
    int c = __ldg(cols + i);
    float nr = __ldg(dis + c);
    uint2 p = __ldg((const uint2*)(h + (size_t)c * 64) + lane);
    float2 f0 = __bfloat1622float2(*reinterpret_cast<const __nv_bfloat162*>(&p.x));
    float2 f1 = __bfloat1622float2(*reinterpret_cast<const __nv_bfloat162*>(&p.y));
    a.x = fmaf(nr, f0.x, a.x); a.y = fmaf(nr, f0.y, a.y);
    a.z = fmaf(nr, f1.x, a.z); a.w = fmaf(nr, f1.y, a.w);
}

// ---------------------------------------------------------------------------
// CSR aggregation (batched, 4-way unrolled), packed bf16x2 output, 256 thr
// ---------------------------------------------------------------------------
__global__ void k_aggregate(const unsigned* __restrict__ h0,
                            const int* __restrict__ offs0, const int* __restrict__ icsr0,
                            const int* __restrict__ cols0,
                            const float* __restrict__ dis0,
                            unsigned* __restrict__ agg0, int n, int bpg)
{
    const int g = blockIdx.x / bpg;
    const int lb = blockIdx.x % bpg;
    int warp = lb * (blockDim.x >> 5) + (threadIdx.x >> 5);
    int lane = threadIdx.x & 31;
    if (warp >= n) return;
    const unsigned* h = h0    + (size_t)g * MAXN * HDIM;
    unsigned* agg     = agg0  + (size_t)g * MAXN * HDIM;
    const int* offs   = offs0 + (size_t)g * MAXN;
    const int* deg    = icsr0 + (size_t)g * ICSR;
    const int* cols   = cols0 + (size_t)g * MAXE;
    const float* dis  = dis0  + (size_t)g * MAXN;

    int s = __ldg(offs + warp);
    int e = s + __ldg(deg + warp);
    float4 a0 = make_float4(0.f, 0.f, 0.f, 0.f);
    float4 a1 = make_float4(0.f, 0.f, 0.f, 0.f);
    float4 a2 = make_float4(0.f, 0.f, 0.f, 0.f);
    float4 a3 = make_float4(0.f, 0.f, 0.f, 0.f);
    int i = s;
    for (; i + 4 <= e; i += 4) {
        agg_step(h, cols, dis, i + 0, lane, a0);
        agg_step(h, cols, dis, i + 1, lane, a1);
        agg_step(h, cols, dis, i + 2, lane, a2);
        agg_step(h, cols, dis, i + 3, lane, a3);
    }
    if (i + 2 <= e) {
        agg_step(h, cols, dis, i + 0, lane, a0);
        agg_step(h, cols, dis, i + 1, lane, a1);
        i += 2;
    }
    if (i < e) agg_step(h, cols, dis, i, lane, a0);
    a0.x += a1.x + a2.x + a3.x;
    a0.y += a1.y + a2.y + a3.y;
    a0.z += a1.z + a2.z + a3.z;
    a0.w += a1.w + a2.w + a3.w;
    uint2 o;
    o.x = pack_bf16x2(a0.x, a0.y);
    o.y = pack_bf16x2(a0.z, a0.w);
    *(uint2*)(agg + (size_t)warp * 64 + lane * 2) = o;
}

// ---------------------------------------------------------------------------
// Fused aggregate + mean-pool (layer 2, batched, 4-way unrolled), 256 thr
// ---------------------------------------------------------------------------
__global__ void k_aggpool(const unsigned* __restrict__ h0,
                          const int* __restrict__ offs0, const int* __restrict__ icsr0,
                          const int* __restrict__ cols0,
                          const float* __restrict__ dis0,
                          float* __restrict__ gsum0, int n, int bpg)
{
    __shared__ float gpart[128];
    if (threadIdx.x < 128) gpart[threadIdx.x] = 0.0f;
    __syncthreads();

    const int g = blockIdx.x / bpg;
    const int lb = blockIdx.x % bpg;
    int warp = lb * (blockDim.x >> 5) + (threadIdx.x >> 5);
    int lane = threadIdx.x & 31;
    const unsigned* h = h0    + (size_t)g * MAXN * HDIM;
    const int* offs   = offs0 + (size_t)g * MAXN;
    const int* deg    = icsr0 + (size_t)g * ICSR;
    const int* cols   = cols0 + (size_t)g * MAXE;
    const float* dis  = dis0  + (size_t)g * MAXN;
    float* gsum       = gsum0 + (size_t)g * HDIM;

    if (warp < n) {
        int s = __ldg(offs + warp);
        int e = s + __ldg(deg + warp);
        float4 a0 = make_float4(0.f, 0.f, 0.f, 0.f);
        float4 a1 = make_float4(0.f, 0.f, 0.f, 0.f);
        float4 a2 = make_float4(0.f, 0.f, 0.f, 0.f);
        float4 a3 = make_float4(0.f, 0.f, 0.f, 0.f);
        int i = s;
        for (; i + 4 <= e; i += 4) {
            agg_step(h, cols, dis, i + 0, lane, a0);
            agg_step(h, cols, dis, i + 1, lane, a1);
            agg_step(h, cols, dis, i + 2, lane, a2);
            agg_step(h, cols, dis, i + 3, lane, a3);
        }
        if (i + 2 <= e) {
            agg_step(h, cols, dis, i + 0, lane, a0);
            agg_step(h, cols, dis, i + 1, lane, a1);
            i += 2;
        }
        if (i < e) agg_step(h, cols, dis, i, lane, a0);
        float d = __ldg(dis + warp);
        atomicAdd(&gpart[lane * 4 + 0], fmaxf(d * (a0.x + a1.x + a2.x + a3.x), 0.f));
        atomicAdd(&gpart[lane * 4 + 1], fmaxf(d * (a0.y + a1.y + a2.y + a3.y), 0.f));
        atomicAdd(&gpart[lane * 4 + 2], fmaxf(d * (a0.z + a1.z + a2.z + a3.z), 0.f));
        atomicAdd(&gpart[lane * 4 + 3], fmaxf(d * (a0.w + a1.w + a2.w + a3.w), 0.f));
    }
    __syncthreads();
    if (threadIdx.x < 128) {
        float v = gpart[threadIdx.x];
        if (v != 0.0f) atomicAdd(&gsum[threadIdx.x], v);
    }
}

// ---------------------------------------------------------------------------
// final MLP
// ---------------------------------------------------------------------------
__global__ void k_final(const float* __restrict__ gsum,
                        const float* __restrict__ w1, const float* __restrict__ b1,
                        const float* __restrict__ w2, const float* __restrict__ b2,
                        float* __restrict__ out, float invN)
{
    __shared__ float cv[512];
    __shared__ float red[128];
    int t = threadIdx.x;
    float a = gsum[t] * invN;
    float b = gsum[128 + t] * invN;
    cv[t]       = a;
    cv[128 + t] = b;
    cv[256 + t] = fabsf(a - b);
    cv[384 + t] = a * b;
    __syncthreads();
    float acc = b1[t];
    for (int k = 0; k < 512; k++)
        acc = fmaf(cv[k], w1[k * 128 + t], acc);
    acc = fmaxf(acc, 0.f);
    red[t] = acc * w2[t];
    __syncthreads();
    for (int s = 64; s > 0; s >>= 1) {
        if (t < s) red[t] += red[t + s];
        __syncthreads();
    }
    if (t == 0) out[0] = red[0] + b2[0];
}

// ---------------------------------------------------------------------------
// launch — single stream, both graphs batched per kernel
// ---------------------------------------------------------------------------
extern "C" void kernel_launch(void* const* d_in, const int* in_sizes, int n_in,
                              void* d_out, int out_size)
{
    const float* x1  = (const float*)d_in[0];
    const int*   ei1 = (const int*)d_in[1];
    const float* x2  = (const float*)d_in[2];
    const int*   ei2 = (const int*)d_in[3];
    const float* enc_w1 = (const float*)d_in[4];
    const float* enc_b1 = (const float*)d_in[5];
    const float* enc_w2 = (const float*)d_in[6];
    const float* enc_b2 = (const float*)d_in[7];
    const float* conv1_w = (const float*)d_in[8];
    const float* conv1_b = (const float*)d_in[9];
    const float* conv2_w = (const float*)d_in[10];
    const float* conv2_b = (const float*)d_in[11];
    const float* sim_w1 = (const float*)d_in[12];
    const float* sim_b1 = (const float*)d_in[13];
    const float* sim_w2 = (const float*)d_in[14];
    const float* sim_b2 = (const float*)d_in[15];

    const int n = in_sizes[0] / HDIM;
    const int E = in_sizes[1] / 2;

    float *bufA, *bufB, *dis, *gsum;
    int *icsr, *offs, *cols, *erank;
    unsigned* wbf;
    cudaGetSymbolAddress((void**)&bufA,  g_bufA);
    cudaGetSymbolAddress((void**)&bufB,  g_bufB);
    cudaGetSymbolAddress((void**)&icsr,  g_icsr);
    cudaGetSymbolAddress((void**)&erank, g_erank);
    cudaGetSymbolAddress((void**)&dis,   g_dis);
    cudaGetSymbolAddress((void**)&offs,  g_offs);
    cudaGetSymbolAddress((void**)&cols,  g_csr_col);
    cudaGetSymbolAddress((void**)&gsum,  g_gsum);
    cudaGetSymbolAddress((void**)&wbf,   g_wbf);

    cudaFuncSetAttribute(k_enc3,   cudaFuncAttributeMaxDynamicSharedMemorySize, SM_ENC3);
    cudaFuncSetAttribute(k_gemm64, cudaFuncAttributeMaxDynamicSharedMemorySize, SM_G64);

    const int tpg128   = (n + 127) / 128;
    const int tpg64    = (n + 63) / 64;
    const int e2Blocks = (E / 2 + 255) / 256;
    const int nBlocks  = (n + 255) / 256;
    const int bpg      = (n * 32 + 255) / 256;

    // --- prep ---
    cudaMemsetAsync(gsum, 0, 2 * HDIM * sizeof(float));
    cudaMemsetAsync(icsr, 0, 2 * ICSR * sizeof(int));
    {
        dim3 grid(32, 4);
        k_convw<<<grid, 256>>>(enc_w1, enc_w2, conv1_w, conv2_w, wbf);
    }

    // --- CSR build (both graphs) ---
    {
        dim3 gE(e2Blocks, 2), gN(nBlocks, 2);
        k_deg2<<<gE, 256>>>(ei1, ei2, E, icsr, erank);
        k_dis_offs2<<<gN, 256>>>(icsr, dis, offs, n);
        k_scatter2<<<gE, 256>>>(ei1, ei2, E, offs, erank, cols);
    }

    // --- fused encoder + conv1 (both graphs) -> bufA (packed bf16x2) ---
    k_enc3<<<2 * tpg128, 256, SM_ENC3>>>(x1, x2, wbf, enc_b1, enc_b2, conv1_b,
                                         (unsigned*)bufA, n, tpg128);

    // --- aggregate 1 -> bufB (packed bf16x2) ---
    k_aggregate<<<2 * bpg, 256>>>((const unsigned*)bufA, offs, icsr, cols, dis,
                                  (unsigned*)bufB, n, bpg);

    // --- GCN layer 2 GEMM (relu(dis*agg) fused) -> bufA (packed bf16x2) ---
    k_gemm64<<<2 * tpg64, 128, SM_G64>>>((const unsigned*)bufB,
                                         wbf + 6 * 8192, wbf + 7 * 8192,
                                         conv2_b, (unsigned*)bufA, dis, n, tpg64);

    // --- aggregate 2 + mean pool -> gsum ---
    k_aggpool<<<2 * bpg, 256>>>((const unsigned*)bufA, offs, icsr, cols, dis,
                                gsum, n, bpg);

    // --- final MLP ---
    k_final<<<1, 128>>>(gsum, sim_w1, sim_b1, sim_w2, sim_b2,
                        (float*)d_out, 1.0f / (float)n);
}